// round 16
// baseline (speedup 1.0000x reference)
#include <cuda_runtime.h>
#include <math.h>

#define B 64
#define H 128
#define E 128
#define NL 4
#define S 8192
#define V 50257
#define FOURH 512
#define CHUNKS 128   // S / ROWS
#define ROWS 64
#define PREFIX 1536                 // inactive blocks before actives
#define NLOGX ((V + 511)/512)       // 99
#define NLOG  (NLOGX*4)             // 396 logits blocks

#define SZ_LOGITS (B*V)
#define OFF_C  (SZ_LOGITS)
#define OFF_H  (OFF_C + NL*B*H)
#define OFF_ATTN (OFF_H + NL*B*H)

typedef unsigned long long ull;

// ---------------- device scratch (no allocations allowed) ----------------
__device__ __align__(16) float g_x[B*H];          // final hidden (x)
__device__ __align__(16) float g_r[B*H];          // Wk @ q  per batch
__device__ float g_cK[B];                          // bk . q
__device__ float g_pl[B*CHUNKS];                   // partial exp-sums
__device__ __align__(16) float g_pacc[B*CHUNKS*H]; // partial weighted sums
__device__ __align__(16) float g_hln[B*H];
__device__ int g_cnt[B];                           // per-batch done counters
__device__ int g_done = 0;                         // LSTM blocks finished
__device__ int g_red  = 0;                         // batches reduced (target 64)
__device__ int g_log  = 0;                         // logits blocks finished

__device__ __forceinline__ float warp_sum(float v) {
#pragma unroll
    for (int o = 16; o > 0; o >>= 1) v += __shfl_xor_sync(0xffffffffu, v, o);
    return v;
}
__device__ __forceinline__ float sigf(float x) { return 1.f / (1.f + __expf(-x)); }

__device__ __forceinline__ ull fma2(ull a, ull b, ull c) {
    ull d;
    asm("fma.rn.f32x2 %0, %1, %2, %3;" : "=l"(d) : "l"(a), "l"(b), "l"(c));
    return d;
}
__device__ __forceinline__ ull bcast2(float f) {
    ull d;
    asm("mov.b64 %0, {%1, %1};" : "=l"(d) : "f"(f));
    return d;
}
__device__ __forceinline__ void spin_on(int* flag, int target) {
    int fv;
    do {
        asm volatile("ld.global.cg.b32 %0, [%1];" : "=r"(fv) : "l"(flag));
        if (fv < target) __nanosleep(64);
    } while (fv < target);
}

// ---------------- shared-memory role layouts (16B-aligned union) ----------
struct __align__(16) LstmSmem {
    ull xs2[2][H];
    ull hs2[2][H];
    float gp[2][2][FOURH];
    float qs[2][H];
};
struct __align__(16) FlashSmem {
    float acc[8][H];
    float l[8];
    float red[128], part[256], cp[H], xsm[H], ctx[H];
};
struct __align__(16) LogitSmem {
    ull hsu[H*8];
};

// ============ LSTM role ====================================================
__device__ void lstm_role(
    LstmSmem& sm, int b0,
    const int* __restrict__ token_id, const float* __restrict__ c0,
    const float* __restrict__ h0, const float* __restrict__ emb,
    const float* __restrict__ Wi, const float* __restrict__ Uh,
    const float* __restrict__ bL, const float* __restrict__ Wq,
    const float* __restrict__ bq, const float* __restrict__ Wk,
    const float* __restrict__ bk, float* __restrict__ out)
{
    int tid = threadIdx.x;

    if (tid == 0) { g_cnt[b0] = 0; g_cnt[b0+1] = 0; }

    for (int idx = tid; idx < 2*H; idx += 256) {
        int bb = idx >> 7, i = idx & 127;
        float v = emb[(size_t)token_id[b0+bb]*E + i];
        sm.xs2[bb][i] = bcast2(v);
    }

    int khalf = tid >> 7;
    int tc = tid & 127;
    int cbase = tc * 4;

    for (int l = 0; l < NL; l++) {
        for (int idx = tid; idx < 2*H; idx += 256) {
            int bb = idx >> 7, i = idx & 127;
            float v = h0[((size_t)l*B + b0 + bb)*H + i];
            sm.hs2[bb][i] = bcast2(v);
        }
        __syncthreads();

        ull a00 = 0, a01 = 0, a10 = 0, a11 = 0;
        const ulonglong2* Wi2 = (const ulonglong2*)(Wi + (size_t)l*E*FOURH);
        const ulonglong2* Uh2 = (const ulonglong2*)(Uh + (size_t)l*H*FOURH);
        int k0 = khalf * 64;
#pragma unroll 4
        for (int k = k0; k < k0 + 64; k++) {
            ulonglong2 w = Wi2[k*(FOURH/4) + tc];
            ulonglong2 u = Uh2[k*(FOURH/4) + tc];
            ull x0 = sm.xs2[0][k], x1 = sm.xs2[1][k];
            ull hh0 = sm.hs2[0][k], hh1 = sm.hs2[1][k];
            a00 = fma2(w.x, x0, a00);  a01 = fma2(w.y, x0, a01);
            a00 = fma2(u.x, hh0, a00); a01 = fma2(u.y, hh0, a01);
            a10 = fma2(w.x, x1, a10);  a11 = fma2(w.y, x1, a11);
            a10 = fma2(u.x, hh1, a10); a11 = fma2(u.y, hh1, a11);
        }
        *(ull*)&sm.gp[khalf][0][cbase]   = a00;
        *(ull*)&sm.gp[khalf][0][cbase+2] = a01;
        *(ull*)&sm.gp[khalf][1][cbase]   = a10;
        *(ull*)&sm.gp[khalf][1][cbase+2] = a11;
        __syncthreads();

        {
            int bb = tid >> 7, i = tid & 127;
            const float* bb_l = bL + l*FOURH;
            float ig = sm.gp[0][bb][i]       + sm.gp[1][bb][i]       + bb_l[i];
            float fg = sm.gp[0][bb][128 + i] + sm.gp[1][bb][128 + i] + bb_l[128 + i];
            float gg = sm.gp[0][bb][256 + i] + sm.gp[1][bb][256 + i] + bb_l[256 + i];
            float og = sm.gp[0][bb][384 + i] + sm.gp[1][bb][384 + i] + bb_l[384 + i];
            size_t ofs = ((size_t)l*B + b0 + bb)*H + i;
            float cprev = c0[ofs];
            float cn = sigf(fg)*cprev + sigf(ig)*tanhf(gg);
            float hn = sigf(og)*tanhf(cn);
            out[OFF_C + ofs] = cn;
            out[OFF_H + ofs] = hn;
            sm.xs2[bb][i] = bcast2(hn);
        }
    }
    __syncthreads();

    for (int idx = tid; idx < 2*H; idx += 256) {
        int bb = idx >> 7, i = idx & 127;
        g_x[(b0+bb)*H + i] = ((const float2*)&sm.xs2[bb][i])->x;
    }

    {
        int bb = tid >> 7, j = tid & 127;
        float acc = bq[j];
#pragma unroll 8
        for (int i = 0; i < H; i++)
            acc += ((const float2*)&sm.xs2[bb][i])->x * Wq[i*H + j];
        sm.qs[bb][j] = acc;
    }
    __syncthreads();

    int wid = tid >> 5, lane = tid & 31;
    for (int row = wid; row < 2*H; row += 8) {
        int bb = row >> 7, i = row & 127;
        float4 wv = ((const float4*)(Wk + (size_t)i*H))[lane];
        float4 qv = ((const float4*)sm.qs[bb])[lane];
        float d = wv.x*qv.x + wv.y*qv.y + wv.z*qv.z + wv.w*qv.w;
        d = warp_sum(d);
        if (lane == 0) g_r[(b0+bb)*H + i] = d;
    }
    if (wid < 2) {
        int bb = wid;
        float p = 0.f;
        for (int j = lane; j < H; j += 32) p += bk[j] * sm.qs[bb][j];
        p = warp_sum(p);
        if (lane == 0) g_cK[b0+bb] = p;
    }
    __syncthreads();
    __threadfence();                    // release g_x/g_r/g_cK/g_cnt
    if (tid == 0) atomicAdd(&g_done, 1);
}

// ============ inline reduce for one batch ==================================
__device__ __noinline__ void reduce_batch(
    int b, int nact, FlashSmem& s,
    const float* __restrict__ Wv, const float* __restrict__ bv,
    const float* __restrict__ Wmix, const float* __restrict__ bmix,
    const float* __restrict__ lns, const float* __restrict__ lnb)
{
    int tid = threadIdx.x;
    int t = tid & 127, half = tid >> 7;

    if (tid < 128)
        s.red[tid] = (tid < nact) ? g_pl[b*CHUNKS + tid] : 0.f;
    __syncthreads();
    for (int o = 64; o > 0; o >>= 1) {
        if (tid < o) s.red[tid] += s.red[tid+o];
        __syncthreads();
    }
    float L = s.red[0];
    __syncthreads();

    {
        float a = 0.f;
#pragma unroll 4
        for (int c = half; c < nact; c += 2)
            a += g_pacc[((size_t)b*CHUNKS + c)*H + t];
        s.part[tid] = a;
    }
    __syncthreads();
    if (tid < 128) {
        s.cp[t] = (s.part[t] + s.part[t+128]) / L;
        s.xsm[t] = g_x[b*H + t];
    }
    __syncthreads();

    {
        float cv = 0.f;
        int i0 = half*64;
#pragma unroll 8
        for (int i = i0; i < i0 + 64; i++) cv += s.cp[i] * Wv[i*H + t];
        s.part[tid] = cv;
    }
    __syncthreads();
    if (tid < 128) s.ctx[t] = s.part[t] + s.part[t+128] + bv[t];
    __syncthreads();

    {
        float hm = 0.f;
        if (half == 0) {
#pragma unroll 8
            for (int i = 0; i < 128; i++) hm += s.xsm[i] * Wmix[i*H + t];
        } else {
#pragma unroll 8
            for (int i = 0; i < 128; i++) hm += s.ctx[i] * Wmix[(H+i)*H + t];
        }
        s.part[tid] = hm;
    }
    __syncthreads();

    float hv = 0.f;
    if (tid < 128) {
        hv = tanhf(s.part[t] + s.part[t+128] + bmix[t]);
        s.red[t] = hv;
    }
    __syncthreads();
    for (int o = 64; o > 0; o >>= 1) {
        if (tid < o) s.red[tid] += s.red[tid+o];
        __syncthreads();
    }
    float mu = s.red[0] * (1.f/128.f);
    __syncthreads();
    float dv = hv - mu;
    if (tid < 128) s.red[t] = dv*dv;
    __syncthreads();
    for (int o = 64; o > 0; o >>= 1) {
        if (tid < o) s.red[tid] += s.red[tid+o];
        __syncthreads();
    }
    float var = s.red[0] * (1.f/128.f);

    if (tid < 128)
        g_hln[b*H + t] = dv * rsqrtf(var + 1e-6f) * lns[t] + lnb[t];

    __syncthreads();
    __threadfence();                 // release g_hln
    if (tid == 0) atomicAdd(&g_red, 1);
}

// ============ logits role ==================================================
__device__ void logits_role(
    LogitSmem& sm, int j,
    const float* __restrict__ Wout, const float* __restrict__ bout,
    float* __restrict__ out)
{
    int tid = threadIdx.x;
    int bq = j / NLOGX;
    int cx = j % NLOGX;

    if (tid == 0) spin_on(&g_red, B);   // all 64 batches reduced
    __syncthreads();
    __threadfence();                    // acquire g_hln

    ull* hsu = sm.hsu;
    float* hsf = (float*)hsu;
    for (int idx = tid; idx < 16*H; idx += 256) {
        int k = idx >> 4, bb = idx & 15;
        hsf[k*16 + bb] = g_hln[(bq*16 + bb)*H + k];
    }
    __syncthreads();

    int base = cx * 512;
    int ca = base + tid;            // column A
    int cb = ca + 256;              // column B
    int ca_ok = (ca < V), cb_ok = (cb < V);
    int ca_c = ca_ok ? ca : (V-1);
    int cb_c = cb_ok ? cb : (V-1);

    ull acc0[8], acc1[8];
#pragma unroll
    for (int i = 0; i < 8; i++) { acc0[i] = 0ULL; acc1[i] = 0ULL; }

#pragma unroll 4
    for (int k = 0; k < H; k++) {
        float wa = Wout[(size_t)k*V + ca_c];
        float wb = Wout[(size_t)k*V + cb_c];
        ull w2a = bcast2(wa);
        ull w2b = bcast2(wb);
        const ulonglong2* hp = (const ulonglong2*)(hsu + k*8);
#pragma unroll
        for (int p = 0; p < 4; p++) {
            ulonglong2 hv = hp[p];
            acc0[2*p]   = fma2(hv.x, w2a, acc0[2*p]);
            acc0[2*p+1] = fma2(hv.y, w2a, acc0[2*p+1]);
            acc1[2*p]   = fma2(hv.x, w2b, acc1[2*p]);
            acc1[2*p+1] = fma2(hv.y, w2b, acc1[2*p+1]);
        }
    }

    if (ca_ok) {
        float bo = bout[ca_c];
#pragma unroll
        for (int p = 0; p < 8; p++) {
            float f0, f1;
            asm("mov.b64 {%0, %1}, %2;" : "=f"(f0), "=f"(f1) : "l"(acc0[p]));
            int b0r = bq*16 + 2*p;
            out[(size_t)b0r*V + ca]     = f0 + bo;
            out[(size_t)(b0r+1)*V + ca] = f1 + bo;
        }
    }
    if (cb_ok) {
        float bo = bout[cb_c];
#pragma unroll
        for (int p = 0; p < 8; p++) {
            float f0, f1;
            asm("mov.b64 {%0, %1}, %2;" : "=f"(f0), "=f"(f1) : "l"(acc1[p]));
            int b0r = bq*16 + 2*p;
            out[(size_t)b0r*V + cb]     = f0 + bo;
            out[(size_t)(b0r+1)*V + cb] = f1 + bo;
        }
    }

    // last logits block resets counters for the next graph replay.
    // Safe: every counter reader in this launch is done by construction.
    __syncthreads();
    if (tid == 0) {
        if (atomicAdd(&g_log, 1) == NLOG - 1) {
            g_done = 0; g_red = 0; g_log = 0;
            __threadfence();
        }
    }
}

// ==== MEGA: LSTM | inactive prefix | actives(+reduce) | logits | trailing ==
__global__ __launch_bounds__(256) void k_mega(
    const float* __restrict__ attn_mem, const int* __restrict__ step_p,
    const int* __restrict__ token_id, const float* __restrict__ c0,
    const float* __restrict__ h0, const float* __restrict__ emb,
    const float* __restrict__ Wi, const float* __restrict__ Uh,
    const float* __restrict__ bL, const float* __restrict__ Wq,
    const float* __restrict__ bq, const float* __restrict__ Wk,
    const float* __restrict__ bk,
    const float* __restrict__ Wv, const float* __restrict__ bv,
    const float* __restrict__ Wmix, const float* __restrict__ bmix,
    const float* __restrict__ lns, const float* __restrict__ lnb,
    const float* __restrict__ Wout, const float* __restrict__ bout,
    float* __restrict__ out)
{
    __shared__ __align__(16) union {
        LstmSmem lstm; FlashSmem fl; LogitSmem lg;
    } sm;
    __shared__ int sm_last;

    int id = blockIdx.x;
    int tid = threadIdx.x, wid = tid >> 5, lane = tid & 31;

    if (id < 32) {
        lstm_role(sm.lstm, id*2, token_id, c0, h0, emb, Wi, Uh, bL,
                  Wq, bq, Wk, bk, out);
        return;
    }

    int step = *step_p;
    int nact = (step >> 6) + 1;          // active chunks per batch
    int nact_u = nact << 6;              // active units
    int ninact_u = CHUNKS*B - nact_u;
    int prefix = PREFIX < ninact_u ? PREFIX : ninact_u;

    int w = id - 32;
    int b, chunk;
    bool active = false;

    if (w < prefix) {
        // early inactive copy (hides LSTM): descending chunks from 127
        b = w & 63; chunk = 127 - (w >> 6);
    } else if (w < prefix + nact_u) {
        int a = w - prefix;
        b = a & 63; chunk = a >> 6; active = true;
    } else if (w < prefix + nact_u + NLOG) {
        logits_role(sm.lg, w - prefix - nact_u, Wout, bout, out);
        return;
    } else {
        int i = w - nact_u - NLOG;       // continue inactive enumeration
        b = i & 63; chunk = 127 - (i >> 6);
    }

    int base = chunk*ROWS + wid*8;
    const float4* src = (const float4*)(attn_mem + (size_t)b*S*H);
    float4* dst = (float4*)(out + OFF_ATTN + (size_t)b*S*H);

    if (!active) {
        float4 v[8];
#pragma unroll
        for (int t = 0; t < 8; t++) v[t] = __ldcs(&src[(size_t)(base+t)*32 + lane]);
#pragma unroll
        for (int t = 0; t < 8; t++) __stcs(&dst[(size_t)(base+t)*32 + lane], v[t]);
        return;
    }

    // ---- active: wait for LSTM results (prefix guarantees near-zero spin)
    if (tid == 0) spin_on(&g_done, 32);
    __syncthreads();
    __threadfence();               // acquire

    float4 rf;
    {
        const float* rp = g_r + b*H + lane*4;
        rf.x = __ldcg(rp); rf.y = __ldcg(rp+1); rf.z = __ldcg(rp+2); rf.w = __ldcg(rp+3);
    }
    float cK = __ldcg(&g_cK[b]);
    const float scl = 0.08838834764831843f;   // 1/sqrt(128)

    float4 v[8];
#pragma unroll
    for (int t = 0; t < 8; t++) {
        int s = base + t;
        if (s == step) {
            const float* xp = g_x + b*H + lane*4;
            v[t].x = __ldcg(xp); v[t].y = __ldcg(xp+1);
            v[t].z = __ldcg(xp+2); v[t].w = __ldcg(xp+3);
        } else {
            v[t] = __ldcs(&src[(size_t)s*32 + lane]);
        }
    }
#pragma unroll
    for (int t = 0; t < 8; t++) __stcs(&dst[(size_t)(base+t)*32 + lane], v[t]);

    float d[8];
#pragma unroll
    for (int t = 0; t < 8; t++)
        d[t] = v[t].x*rf.x + v[t].y*rf.y + v[t].z*rf.z + v[t].w*rf.w;
#pragma unroll
    for (int o = 16; o > 0; o >>= 1) {
#pragma unroll
        for (int t = 0; t < 8; t++)
            d[t] += __shfl_xor_sync(0xffffffffu, d[t], o);
    }

    // no-max softmax partials: scores are O(1), fp32 exp is safe
    float l = 0.f;
    float4 acc = {0.f, 0.f, 0.f, 0.f};
#pragma unroll
    for (int t = 0; t < 8; t++) {
        float ww = (base + t <= step) ? __expf((d[t] + cK) * scl) : 0.f;
        l += ww;
        acc.x += ww*v[t].x; acc.y += ww*v[t].y;
        acc.z += ww*v[t].z; acc.w += ww*v[t].w;
    }
    ((float4*)sm.fl.acc[wid])[lane] = acc;
    if (lane == 0) sm.fl.l[wid] = l;
    __syncthreads();

    if (tid < H) {
        float a = 0.f;
#pragma unroll
        for (int ww = 0; ww < 8; ww++) a += sm.fl.acc[ww][tid];
        g_pacc[((size_t)b*CHUNKS + chunk)*H + tid] = a;
    }
    if (tid == 0) {
        float L = 0.f;
#pragma unroll
        for (int ww = 0; ww < 8; ww++) L += sm.fl.l[ww];
        g_pl[b*CHUNKS + chunk] = L;
    }

    // last-done block for this batch runs the reduce inline (bumps g_red)
    __threadfence();               // publish pacc/pl
    __syncthreads();
    if (tid == 0) {
        int old = atomicAdd(&g_cnt[b], 1);
        sm_last = (old == nact - 1);
    }
    __syncthreads();
    if (sm_last) {
        __threadfence();           // acquire all blocks' partials
        reduce_batch(b, nact, sm.fl, Wv, bv, Wmix, bmix, lns, lnb);
    }
}

// ==========================================================================
extern "C" void kernel_launch(void* const* d_in, const int* in_sizes, int n_in,
                              void* d_out, int out_size)
{
    const int*   token_id = (const int*)  d_in[0];
    const float* c0       = (const float*)d_in[1];
    const float* h0       = (const float*)d_in[2];
    const float* attn_mem = (const float*)d_in[3];
    const int*   step_p   = (const int*)  d_in[4];
    const float* emb      = (const float*)d_in[5];
    const float* Wi       = (const float*)d_in[6];
    const float* Uh       = (const float*)d_in[7];
    const float* bL       = (const float*)d_in[8];
    const float* Wq       = (const float*)d_in[9];
    const float* bq       = (const float*)d_in[10];
    const float* Wk       = (const float*)d_in[11];
    const float* bk       = (const float*)d_in[12];
    const float* Wv       = (const float*)d_in[13];
    const float* bv       = (const float*)d_in[14];
    const float* Wmix     = (const float*)d_in[15];
    const float* bmix     = (const float*)d_in[16];
    const float* lns      = (const float*)d_in[17];
    const float* lnb      = (const float*)d_in[18];
    const float* Wout     = (const float*)d_in[19];
    const float* bout     = (const float*)d_in[20];
    float* out = (float*)d_out;

    int grid = 32 + CHUNKS*B + NLOG;   // 32 + 8192 + 396 = 8620
    k_mega<<<grid, 256>>>(attn_mem, step_p, token_id, c0, h0, emb,
                          Wi, Uh, bL, Wq, bq, Wk, bk,
                          Wv, bv, Wmix, bmix, lns, lnb, Wout, bout, out);
}

// round 17
// speedup vs baseline: 1.0588x; 1.0588x over previous
#include <cuda_runtime.h>
#include <math.h>

#define B 64
#define H 128
#define E 128
#define NL 4
#define S 8192
#define V 50257
#define FOURH 512
#define CHUNKS 128   // S / ROWS
#define ROWS 64
#define PREFIX 1536                 // inactive blocks before actives
#define NLOGX ((V + 511)/512)       // 99
#define NLOG  (NLOGX*4)             // 396 logits blocks

#define SZ_LOGITS (B*V)
#define OFF_C  (SZ_LOGITS)
#define OFF_H  (OFF_C + NL*B*H)
#define OFF_ATTN (OFF_H + NL*B*H)

typedef unsigned long long ull;

// ---------------- device scratch (no allocations allowed) ----------------
__device__ __align__(16) float g_x[B*H];          // final hidden (x)
__device__ __align__(16) float g_r[B*H];          // Wk @ q  per batch
__device__ float g_cK[B];                          // bk . q
__device__ float g_pl[B*CHUNKS];                   // partial exp-sums
__device__ __align__(16) float g_pacc[B*CHUNKS*H]; // partial weighted sums
__device__ __align__(16) float g_hln[B*H];
__device__ int g_cnt[B];                           // per-batch done counters
__device__ int g_done = 0;                         // LSTM blocks finished
__device__ int g_red  = 0;                         // batches reduced (target 64)
__device__ int g_log  = 0;                         // logits blocks finished

__device__ __forceinline__ float warp_sum(float v) {
#pragma unroll
    for (int o = 16; o > 0; o >>= 1) v += __shfl_xor_sync(0xffffffffu, v, o);
    return v;
}
__device__ __forceinline__ float sigf(float x) { return 1.f / (1.f + __expf(-x)); }

__device__ __forceinline__ ull fma2(ull a, ull b, ull c) {
    ull d;
    asm("fma.rn.f32x2 %0, %1, %2, %3;" : "=l"(d) : "l"(a), "l"(b), "l"(c));
    return d;
}
__device__ __forceinline__ ull bcast2(float f) {
    ull d;
    asm("mov.b64 %0, {%1, %1};" : "=l"(d) : "f"(f));
    return d;
}
__device__ __forceinline__ void spin_on(int* flag, int target) {
    int fv;
    do {
        asm volatile("ld.global.cg.b32 %0, [%1];" : "=r"(fv) : "l"(flag));
        if (fv < target) __nanosleep(64);
    } while (fv < target);
}

// ---------------- shared-memory role layouts (16B-aligned union) ----------
struct __align__(16) LstmSmem {
    ull xs2[2][H];
    ull hs2[2][H];
    float gp[2][2][FOURH];
    float qs[2][H];
};
struct __align__(16) FlashSmem {
    float acc[8][H];
    float l[8];
    float red[128], part[256], cp[H], xsm[H], ctx[H];
};
struct __align__(16) LogitSmem {
    ull hsu[H*8];
};

// ============ LSTM role ====================================================
__device__ void lstm_role(
    LstmSmem& sm, int b0,
    const int* __restrict__ token_id, const float* __restrict__ c0,
    const float* __restrict__ h0, const float* __restrict__ emb,
    const float* __restrict__ Wi, const float* __restrict__ Uh,
    const float* __restrict__ bL, const float* __restrict__ Wq,
    const float* __restrict__ bq, const float* __restrict__ Wk,
    const float* __restrict__ bk, float* __restrict__ out)
{
    int tid = threadIdx.x;

    if (tid == 0) { g_cnt[b0] = 0; g_cnt[b0+1] = 0; }

    for (int idx = tid; idx < 2*H; idx += 256) {
        int bb = idx >> 7, i = idx & 127;
        float v = emb[(size_t)token_id[b0+bb]*E + i];
        sm.xs2[bb][i] = bcast2(v);
    }

    int khalf = tid >> 7;
    int tc = tid & 127;
    int cbase = tc * 4;

    for (int l = 0; l < NL; l++) {
        for (int idx = tid; idx < 2*H; idx += 256) {
            int bb = idx >> 7, i = idx & 127;
            float v = h0[((size_t)l*B + b0 + bb)*H + i];
            sm.hs2[bb][i] = bcast2(v);
        }
        __syncthreads();

        ull a00 = 0, a01 = 0, a10 = 0, a11 = 0;
        const ulonglong2* Wi2 = (const ulonglong2*)(Wi + (size_t)l*E*FOURH);
        const ulonglong2* Uh2 = (const ulonglong2*)(Uh + (size_t)l*H*FOURH);
        int k0 = khalf * 64;
#pragma unroll 4
        for (int k = k0; k < k0 + 64; k++) {
            ulonglong2 w = Wi2[k*(FOURH/4) + tc];
            ulonglong2 u = Uh2[k*(FOURH/4) + tc];
            ull x0 = sm.xs2[0][k], x1 = sm.xs2[1][k];
            ull hh0 = sm.hs2[0][k], hh1 = sm.hs2[1][k];
            a00 = fma2(w.x, x0, a00);  a01 = fma2(w.y, x0, a01);
            a00 = fma2(u.x, hh0, a00); a01 = fma2(u.y, hh0, a01);
            a10 = fma2(w.x, x1, a10);  a11 = fma2(w.y, x1, a11);
            a10 = fma2(u.x, hh1, a10); a11 = fma2(u.y, hh1, a11);
        }
        *(ull*)&sm.gp[khalf][0][cbase]   = a00;
        *(ull*)&sm.gp[khalf][0][cbase+2] = a01;
        *(ull*)&sm.gp[khalf][1][cbase]   = a10;
        *(ull*)&sm.gp[khalf][1][cbase+2] = a11;
        __syncthreads();

        {
            int bb = tid >> 7, i = tid & 127;
            const float* bb_l = bL + l*FOURH;
            float ig = sm.gp[0][bb][i]       + sm.gp[1][bb][i]       + bb_l[i];
            float fg = sm.gp[0][bb][128 + i] + sm.gp[1][bb][128 + i] + bb_l[128 + i];
            float gg = sm.gp[0][bb][256 + i] + sm.gp[1][bb][256 + i] + bb_l[256 + i];
            float og = sm.gp[0][bb][384 + i] + sm.gp[1][bb][384 + i] + bb_l[384 + i];
            size_t ofs = ((size_t)l*B + b0 + bb)*H + i;
            float cprev = c0[ofs];
            float cn = sigf(fg)*cprev + sigf(ig)*tanhf(gg);
            float hn = sigf(og)*tanhf(cn);
            out[OFF_C + ofs] = cn;
            out[OFF_H + ofs] = hn;
            sm.xs2[bb][i] = bcast2(hn);
        }
    }
    __syncthreads();

    for (int idx = tid; idx < 2*H; idx += 256) {
        int bb = idx >> 7, i = idx & 127;
        g_x[(b0+bb)*H + i] = ((const float2*)&sm.xs2[bb][i])->x;
    }

    {
        int bb = tid >> 7, j = tid & 127;
        float acc = bq[j];
#pragma unroll 8
        for (int i = 0; i < H; i++)
            acc += ((const float2*)&sm.xs2[bb][i])->x * Wq[i*H + j];
        sm.qs[bb][j] = acc;
    }
    __syncthreads();

    int wid = tid >> 5, lane = tid & 31;
    for (int row = wid; row < 2*H; row += 8) {
        int bb = row >> 7, i = row & 127;
        float4 wv = ((const float4*)(Wk + (size_t)i*H))[lane];
        float4 qv = ((const float4*)sm.qs[bb])[lane];
        float d = wv.x*qv.x + wv.y*qv.y + wv.z*qv.z + wv.w*qv.w;
        d = warp_sum(d);
        if (lane == 0) g_r[(b0+bb)*H + i] = d;
    }
    if (wid < 2) {
        int bb = wid;
        float p = 0.f;
        for (int j = lane; j < H; j += 32) p += bk[j] * sm.qs[bb][j];
        p = warp_sum(p);
        if (lane == 0) g_cK[b0+bb] = p;
    }
    __syncthreads();
    __threadfence();                    // release g_x/g_r/g_cK/g_cnt
    if (tid == 0) atomicAdd(&g_done, 1);
}

// ============ inline reduce for one batch ==================================
__device__ __noinline__ void reduce_batch(
    int b, int nact, FlashSmem& s,
    const float* __restrict__ Wv, const float* __restrict__ bv,
    const float* __restrict__ Wmix, const float* __restrict__ bmix,
    const float* __restrict__ lns, const float* __restrict__ lnb)
{
    int tid = threadIdx.x;
    int t = tid & 127, half = tid >> 7;

    if (tid < 128)
        s.red[tid] = (tid < nact) ? g_pl[b*CHUNKS + tid] : 0.f;
    __syncthreads();
    for (int o = 64; o > 0; o >>= 1) {
        if (tid < o) s.red[tid] += s.red[tid+o];
        __syncthreads();
    }
    float L = s.red[0];
    __syncthreads();

    {
        float a = 0.f;
#pragma unroll 4
        for (int c = half; c < nact; c += 2)
            a += g_pacc[((size_t)b*CHUNKS + c)*H + t];
        s.part[tid] = a;
    }
    __syncthreads();
    if (tid < 128) {
        s.cp[t] = (s.part[t] + s.part[t+128]) / L;
        s.xsm[t] = g_x[b*H + t];
    }
    __syncthreads();

    {
        float cv = 0.f;
        int i0 = half*64;
#pragma unroll 8
        for (int i = i0; i < i0 + 64; i++) cv += s.cp[i] * Wv[i*H + t];
        s.part[tid] = cv;
    }
    __syncthreads();
    if (tid < 128) s.ctx[t] = s.part[t] + s.part[t+128] + bv[t];
    __syncthreads();

    {
        float hm = 0.f;
        if (half == 0) {
#pragma unroll 8
            for (int i = 0; i < 128; i++) hm += s.xsm[i] * Wmix[i*H + t];
        } else {
#pragma unroll 8
            for (int i = 0; i < 128; i++) hm += s.ctx[i] * Wmix[(H+i)*H + t];
        }
        s.part[tid] = hm;
    }
    __syncthreads();

    float hv = 0.f;
    if (tid < 128) {
        hv = tanhf(s.part[t] + s.part[t+128] + bmix[t]);
        s.red[t] = hv;
    }
    __syncthreads();
    for (int o = 64; o > 0; o >>= 1) {
        if (tid < o) s.red[tid] += s.red[tid+o];
        __syncthreads();
    }
    float mu = s.red[0] * (1.f/128.f);
    __syncthreads();
    float dv = hv - mu;
    if (tid < 128) s.red[t] = dv*dv;
    __syncthreads();
    for (int o = 64; o > 0; o >>= 1) {
        if (tid < o) s.red[tid] += s.red[tid+o];
        __syncthreads();
    }
    float var = s.red[0] * (1.f/128.f);

    if (tid < 128)
        g_hln[b*H + t] = dv * rsqrtf(var + 1e-6f) * lns[t] + lnb[t];

    __syncthreads();
    __threadfence();                 // release g_hln
    if (tid == 0) atomicAdd(&g_red, 1);
}

// ============ logits role ==================================================
__device__ void logits_role(
    LogitSmem& sm, int j,
    const float* __restrict__ Wout, const float* __restrict__ bout,
    float* __restrict__ out)
{
    int tid = threadIdx.x;
    int bq = j / NLOGX;
    int cx = j % NLOGX;

    // producers retired ~2000 blocks ago -> spin is effectively free
    if (tid == 0) spin_on(&g_red, B);
    __syncthreads();
    __threadfence();                    // acquire g_hln

    ull* hsu = sm.hsu;
    float* hsf = (float*)hsu;
    for (int idx = tid; idx < 16*H; idx += 256) {
        int k = idx >> 4, bb = idx & 15;
        hsf[k*16 + bb] = g_hln[(bq*16 + bb)*H + k];
    }
    __syncthreads();

    int base = cx * 512;
    int ca = base + tid;            // column A
    int cb = ca + 256;              // column B
    int ca_ok = (ca < V), cb_ok = (cb < V);
    int ca_c = ca_ok ? ca : (V-1);
    int cb_c = cb_ok ? cb : (V-1);

    ull acc0[8], acc1[8];
#pragma unroll
    for (int i = 0; i < 8; i++) { acc0[i] = 0ULL; acc1[i] = 0ULL; }

#pragma unroll 4
    for (int k = 0; k < H; k++) {
        float wa = Wout[(size_t)k*V + ca_c];
        float wb = Wout[(size_t)k*V + cb_c];
        ull w2a = bcast2(wa);
        ull w2b = bcast2(wb);
        const ulonglong2* hp = (const ulonglong2*)(hsu + k*8);
#pragma unroll
        for (int p = 0; p < 4; p++) {
            ulonglong2 hv = hp[p];
            acc0[2*p]   = fma2(hv.x, w2a, acc0[2*p]);
            acc0[2*p+1] = fma2(hv.y, w2a, acc0[2*p+1]);
            acc1[2*p]   = fma2(hv.x, w2b, acc1[2*p]);
            acc1[2*p+1] = fma2(hv.y, w2b, acc1[2*p+1]);
        }
    }

    if (ca_ok) {
        float bo = bout[ca_c];
#pragma unroll
        for (int p = 0; p < 8; p++) {
            float f0, f1;
            asm("mov.b64 {%0, %1}, %2;" : "=f"(f0), "=f"(f1) : "l"(acc0[p]));
            int b0r = bq*16 + 2*p;
            out[(size_t)b0r*V + ca]     = f0 + bo;
            out[(size_t)(b0r+1)*V + ca] = f1 + bo;
        }
    }
    if (cb_ok) {
        float bo = bout[cb_c];
#pragma unroll
        for (int p = 0; p < 8; p++) {
            float f0, f1;
            asm("mov.b64 {%0, %1}, %2;" : "=f"(f0), "=f"(f1) : "l"(acc1[p]));
            int b0r = bq*16 + 2*p;
            out[(size_t)b0r*V + cb]     = f0 + bo;
            out[(size_t)(b0r+1)*V + cb] = f1 + bo;
        }
    }

    // last logits block resets counters for the next graph replay.
    // Safe: the blocks after logits are pure copies reading no counters.
    __syncthreads();
    if (tid == 0) {
        if (atomicAdd(&g_log, 1) == NLOG - 1) {
            g_done = 0; g_red = 0; g_log = 0;
            __threadfence();
        }
    }
}

// ==== MEGA: LSTM | prefix copy | actives(+reduce) | copy A | logits | copy B
__global__ __launch_bounds__(256) void k_mega(
    const float* __restrict__ attn_mem, const int* __restrict__ step_p,
    const int* __restrict__ token_id, const float* __restrict__ c0,
    const float* __restrict__ h0, const float* __restrict__ emb,
    const float* __restrict__ Wi, const float* __restrict__ Uh,
    const float* __restrict__ bL, const float* __restrict__ Wq,
    const float* __restrict__ bq, const float* __restrict__ Wk,
    const float* __restrict__ bk,
    const float* __restrict__ Wv, const float* __restrict__ bv,
    const float* __restrict__ Wmix, const float* __restrict__ bmix,
    const float* __restrict__ lns, const float* __restrict__ lnb,
    const float* __restrict__ Wout, const float* __restrict__ bout,
    float* __restrict__ out)
{
    __shared__ __align__(16) union {
        LstmSmem lstm; FlashSmem fl; LogitSmem lg;
    } sm;
    __shared__ int sm_last;

    int id = blockIdx.x;
    int tid = threadIdx.x, wid = tid >> 5, lane = tid & 31;

    if (id < 32) {
        lstm_role(sm.lstm, id*2, token_id, c0, h0, emb, Wi, Uh, bL,
                  Wq, bq, Wk, bk, out);
        return;
    }

    int step = *step_p;
    int nact = (step >> 6) + 1;          // active chunks per batch
    int nact_u = nact << 6;              // active units
    int ninact_u = CHUNKS*B - nact_u;
    int prefix = PREFIX < ninact_u ? PREFIX : ninact_u;
    // trailing-A so that exactly min(NLOG, remaining) inactive blocks follow
    int tailB = NLOG < (ninact_u - prefix) ? NLOG : (ninact_u - prefix);
    int q1 = prefix + nact_u;                       // end of actives
    int q2 = q1 + (ninact_u - prefix - tailB);      // end of trailing A
    int q3 = q2 + NLOG;                             // end of logits

    int w = id - 32;
    int b, chunk;
    bool active = false;

    if (w < prefix) {
        b = w & 63; chunk = 127 - (w >> 6);          // early inactive
    } else if (w < q1) {
        int a = w - prefix;
        b = a & 63; chunk = a >> 6; active = true;   // active
    } else if (w < q2) {
        int i = w - nact_u;                          // trailing A inactive
        b = i & 63; chunk = 127 - (i >> 6);
    } else if (w < q3) {
        logits_role(sm.lg, w - q2, Wout, bout, out); // logits (late)
        return;
    } else {
        int i = w - nact_u - NLOG;                   // trailing B inactive
        b = i & 63; chunk = 127 - (i >> 6);
    }

    int base = chunk*ROWS + wid*8;
    const float4* src = (const float4*)(attn_mem + (size_t)b*S*H);
    float4* dst = (float4*)(out + OFF_ATTN + (size_t)b*S*H);

    if (!active) {
        float4 v[8];
#pragma unroll
        for (int t = 0; t < 8; t++) v[t] = __ldcs(&src[(size_t)(base+t)*32 + lane]);
#pragma unroll
        for (int t = 0; t < 8; t++) __stcs(&dst[(size_t)(base+t)*32 + lane], v[t]);
        return;
    }

    // ---- active: wait for LSTM results (prefix guarantees near-zero spin)
    if (tid == 0) spin_on(&g_done, 32);
    __syncthreads();
    __threadfence();               // acquire

    float4 rf;
    {
        const float* rp = g_r + b*H + lane*4;
        rf.x = __ldcg(rp); rf.y = __ldcg(rp+1); rf.z = __ldcg(rp+2); rf.w = __ldcg(rp+3);
    }
    float cK = __ldcg(&g_cK[b]);
    const float scl = 0.08838834764831843f;   // 1/sqrt(128)

    float4 v[8];
#pragma unroll
    for (int t = 0; t < 8; t++) {
        int s = base + t;
        if (s == step) {
            const float* xp = g_x + b*H + lane*4;
            v[t].x = __ldcg(xp); v[t].y = __ldcg(xp+1);
            v[t].z = __ldcg(xp+2); v[t].w = __ldcg(xp+3);
        } else {
            v[t] = __ldcs(&src[(size_t)s*32 + lane]);
        }
    }
#pragma unroll
    for (int t = 0; t < 8; t++) __stcs(&dst[(size_t)(base+t)*32 + lane], v[t]);

    float d[8];
#pragma unroll
    for (int t = 0; t < 8; t++)
        d[t] = v[t].x*rf.x + v[t].y*rf.y + v[t].z*rf.z + v[t].w*rf.w;
#pragma unroll
    for (int o = 16; o > 0; o >>= 1) {
#pragma unroll
        for (int t = 0; t < 8; t++)
            d[t] += __shfl_xor_sync(0xffffffffu, d[t], o);
    }

    // no-max softmax partials: scores are O(1), fp32 exp is safe
    float l = 0.f;
    float4 acc = {0.f, 0.f, 0.f, 0.f};
#pragma unroll
    for (int t = 0; t < 8; t++) {
        float ww = (base + t <= step) ? __expf((d[t] + cK) * scl) : 0.f;
        l += ww;
        acc.x += ww*v[t].x; acc.y += ww*v[t].y;
        acc.z += ww*v[t].z; acc.w += ww*v[t].w;
    }
    ((float4*)sm.fl.acc[wid])[lane] = acc;
    if (lane == 0) sm.fl.l[wid] = l;
    __syncthreads();

    if (tid < H) {
        float a = 0.f;
#pragma unroll
        for (int ww = 0; ww < 8; ww++) a += sm.fl.acc[ww][tid];
        g_pacc[((size_t)b*CHUNKS + chunk)*H + tid] = a;
    }
    if (tid == 0) {
        float L = 0.f;
#pragma unroll
        for (int ww = 0; ww < 8; ww++) L += sm.fl.l[ww];
        g_pl[b*CHUNKS + chunk] = L;
    }

    // last-done block for this batch runs the reduce inline (bumps g_red)
    __threadfence();               // publish pacc/pl
    __syncthreads();
    if (tid == 0) {
        int old = atomicAdd(&g_cnt[b], 1);
        sm_last = (old == nact - 1);
    }
    __syncthreads();
    if (sm_last) {
        __threadfence();           // acquire all blocks' partials
        reduce_batch(b, nact, sm.fl, Wv, bv, Wmix, bmix, lns, lnb);
    }
}

// ==========================================================================
extern "C" void kernel_launch(void* const* d_in, const int* in_sizes, int n_in,
                              void* d_out, int out_size)
{
    const int*   token_id = (const int*)  d_in[0];
    const float* c0       = (const float*)d_in[1];
    const float* h0       = (const float*)d_in[2];
    const float* attn_mem = (const float*)d_in[3];
    const int*   step_p   = (const int*)  d_in[4];
    const float* emb      = (const float*)d_in[5];
    const float* Wi       = (const float*)d_in[6];
    const float* Uh       = (const float*)d_in[7];
    const float* bL       = (const float*)d_in[8];
    const float* Wq       = (const float*)d_in[9];
    const float* bq       = (const float*)d_in[10];
    const float* Wk       = (const float*)d_in[11];
    const float* bk       = (const float*)d_in[12];
    const float* Wv       = (const float*)d_in[13];
    const float* bv       = (const float*)d_in[14];
    const float* Wmix     = (const float*)d_in[15];
    const float* bmix     = (const float*)d_in[16];
    const float* lns      = (const float*)d_in[17];
    const float* lnb      = (const float*)d_in[18];
    const float* Wout     = (const float*)d_in[19];
    const float* bout     = (const float*)d_in[20];
    float* out = (float*)d_out;

    int grid = 32 + CHUNKS*B + NLOG;   // 32 + 8192 + 396 = 8620
    k_mega<<<grid, 256>>>(attn_mem, step_p, token_id, c0, h0, emb,
                          Wi, Uh, bL, Wq, bq, Wk, bk,
                          Wv, bv, Wmix, bmix, lns, lnb, Wout, bout, out);
}